// round 7
// baseline (speedup 1.0000x reference)
#include <cuda_runtime.h>
#include <cuda_bf16.h>
#include <stdint.h>
#include <math.h>

#define BB 8
#define HH 64
#define WW 64
#define CC 256
#define NPIX (BB*HH*WW)          // 32768

// ---------------- device scratch ----------------
__device__ __nv_bfloat16 g_yhi[NPIX*CC];
__device__ __nv_bfloat16 g_ylo[NPIX*CC];
__device__ __nv_bfloat16 g_Whi[CC*CC];
__device__ __nv_bfloat16 g_Wlo[CC*CC];

// ---------------- helpers ----------------
__device__ __forceinline__ uint32_t smem_u32(const void* p) {
    uint32_t a;
    asm("{ .reg .u64 t; cvta.to.shared.u64 t, %1; cvt.u32.u64 %0, t; }" : "=r"(a) : "l"(p));
    return a;
}
__device__ __forceinline__ uint64_t gmem_u64(const void* p) {
    uint64_t a;
    asm("cvta.to.global.u64 %0, %1;" : "=l"(a) : "l"(p));
    return a;
}
#define CP_ASYNC16(sa, ga) \
    asm volatile("cp.async.cg.shared.global [%0], [%1], 16;" :: "r"(sa), "l"(ga))
#define CP_COMMIT() asm volatile("cp.async.commit_group;")
#define CP_WAIT(n)  asm volatile("cp.async.wait_group %0;" :: "n"(n))

#define LDMATRIX_X4(r0, r1, r2, r3, addr) \
    asm volatile("ldmatrix.sync.aligned.m8n8.x4.shared.b16 {%0,%1,%2,%3}, [%4];" \
        : "=r"(r0), "=r"(r1), "=r"(r2), "=r"(r3) : "r"(addr))

#define MMA_16816(c, a, b0, b1) \
    asm volatile("mma.sync.aligned.m16n8k16.row.col.f32.bf16.bf16.f32 " \
        "{%0,%1,%2,%3}, {%4,%5,%6,%7}, {%8,%9}, {%0,%1,%2,%3};" \
        : "+f"((c)[0]), "+f"((c)[1]), "+f"((c)[2]), "+f"((c)[3]) \
        : "r"((a)[0]), "r"((a)[1]), "r"((a)[2]), "r"((a)[3]), "r"(b0), "r"(b1))

static __device__ __forceinline__ void split_bf16(float v, __nv_bfloat16& hi, __nv_bfloat16& lo) {
    hi = __float2bfloat16_rn(v);
    lo = __float2bfloat16_rn(v - __bfloat162float(hi));
}
static __device__ __forceinline__ float4 f4add(float4 a, float4 b) {
    return make_float4(a.x+b.x, a.y+b.y, a.z+b.z, a.w+b.w);
}
static __device__ __forceinline__ float4 shfl_up4(float4 v) {
    float4 r;
    r.x = __shfl_up_sync(0xFFFFFFFFu, v.x, 1);
    r.y = __shfl_up_sync(0xFFFFFFFFu, v.y, 1);
    r.z = __shfl_up_sync(0xFFFFFFFFu, v.z, 1);
    r.w = __shfl_up_sync(0xFFFFFFFFu, v.w, 1);
    return r;
}
static __device__ __forceinline__ float4 shfl_dn4(float4 v) {
    float4 r;
    r.x = __shfl_down_sync(0xFFFFFFFFu, v.x, 1);
    r.y = __shfl_down_sync(0xFFFFFFFFu, v.y, 1);
    r.z = __shfl_down_sync(0xFFFFFFFFu, v.z, 1);
    r.w = __shfl_down_sync(0xFFFFFFFFu, v.w, 1);
    return r;
}

// ============================================================================
// K1: prep.
//  Blocks [0,512): blur, barrier-free. Block = (b, 8-row hseg, 8-c4 cgroup).
//   Warp covers 32 consecutive w for 2 c4 items; horizontal neighbors via
//   shuffles; vertical via 3-deep register ring. NO smem, NO syncthreads.
//  Blocks [512,576): W = proj_w @ v_w -> (g_Whi, g_Wlo).
// ============================================================================
__global__ __launch_bounds__(256) void prep_kernel(const float* __restrict__ x,
                                                   const float* __restrict__ vw,
                                                   const float* __restrict__ pw) {
    int bid = blockIdx.x;
    int tid = threadIdx.x;
    if (bid < 512) {
        int b  = bid >> 6;            // 8
        int hs = (bid >> 3) & 7;      // 8 segments of 8 rows
        int cg = bid & 7;             // 8 channel groups (8 c4 each)
        int h0 = hs * 8;
        int warp = tid >> 5;
        int lane = tid & 31;
        int whalf = warp & 1;         // w 0-31 / 32-63
        int cp    = warp >> 1;        // 0..3 -> c4 pair within group
        int w  = whalf * 32 + lane;
        int c4a = cg * 8 + cp * 2;    // items: c4a, c4a+1
        const float e  = 2.718281828459045f;
        const float wo = 1.0f / (e + 8.0f);
        const float wd = e * wo - wo;
        const float4 Z = make_float4(0.f, 0.f, 0.f, 0.f);
        const float4* x4 = (const float4*)x;

        float4 hs0[2] = {Z, Z}, hs1[2] = {Z, Z};
        float4 xl0[2] = {Z, Z}, xl1[2] = {Z, Z};

        #pragma unroll
        for (int r = h0 - 1; r <= h0 + 8; r++) {
            bool inr = (r >= 0) && (r < HH);
            float4 o2hi[2]; float4 o2lo_dummy; (void)o2lo_dummy;
            uint2 HiU[2], LoU[2];
            #pragma unroll
            for (int it = 0; it < 2; it++) {
                int c4 = c4a + it;
                float4 xc = Z, xb = Z;
                if (inr) {
                    size_t rb = (((size_t)b * HH + r) * WW) * 64 + c4;
                    xc = x4[rb + (size_t)w * 64];
                    if (lane == 0 && w > 0)       xb = x4[rb + (size_t)(w - 1) * 64];
                    else if (lane == 31 && w < 63) xb = x4[rb + (size_t)(w + 1) * 64];
                }
                float4 xl = shfl_up4(xc);
                if (lane == 0) xl = (w > 0) ? xb : Z;
                float4 xr = shfl_dn4(xc);
                if (lane == 31) xr = (w < 63) ? xb : Z;
                float4 hsum = f4add(f4add(xl, xc), xr);

                if (r >= h0 + 1) {
                    float4 o;
                    o.x = wo * (hs0[it].x + hs1[it].x + hsum.x) + wd * xl0[it].x;
                    o.y = wo * (hs0[it].y + hs1[it].y + hsum.y) + wd * xl0[it].y;
                    o.z = wo * (hs0[it].z + hs1[it].z + hsum.z) + wd * xl0[it].z;
                    o.w = wo * (hs0[it].w + hs1[it].w + hsum.w) + wd * xl0[it].w;
                    union { __nv_bfloat16 h4[4]; uint2 u; } Hi, Lo;
                    split_bf16(o.x, Hi.h4[0], Lo.h4[0]);
                    split_bf16(o.y, Hi.h4[1], Lo.h4[1]);
                    split_bf16(o.z, Hi.h4[2], Lo.h4[2]);
                    split_bf16(o.w, Hi.h4[3], Lo.h4[3]);
                    HiU[it] = Hi.u; LoU[it] = Lo.u;
                }
                hs0[it] = hs1[it]; hs1[it] = hsum;
                xl0[it] = xl1[it]; xl1[it] = xl;
            }
            if (r >= h0 + 1) {
                int h = r - 1;
                // items are adjacent uint2 -> one uint4 store each for hi/lo
                size_t pix = ((size_t)b * HH + h) * WW + w;
                size_t q = pix * 32 + cg * 4 + cp;      // uint4 index
                ((uint4*)g_yhi)[q] = make_uint4(HiU[0].x, HiU[0].y, HiU[1].x, HiU[1].y);
                ((uint4*)g_ylo)[q] = make_uint4(LoU[0].x, LoU[0].y, LoU[1].x, LoU[1].y);
            }
        }
    } else {
        int q  = bid - 512;
        int e0 = (q >> 3) * 32;
        int c0 = (q & 7) * 32;
        int er = e0 + (tid >> 3);
        int cc = c0 + (tid & 7) * 4;
        float a0 = 0.f, a1 = 0.f, a2 = 0.f, a3 = 0.f;
        const float* prow = pw + er * 256;
        #pragma unroll 8
        for (int d = 0; d < 256; d++) {
            float a = prow[d];
            float4 v = *(const float4*)(vw + d * 256 + cc);
            a0 += a * v.x; a1 += a * v.y; a2 += a * v.z; a3 += a * v.w;
        }
        union { __nv_bfloat16 h4[4]; uint2 u; } Hi, Lo;
        split_bf16(a0, Hi.h4[0], Lo.h4[0]);
        split_bf16(a1, Hi.h4[1], Lo.h4[1]);
        split_bf16(a2, Hi.h4[2], Lo.h4[2]);
        split_bf16(a3, Hi.h4[3], Lo.h4[3]);
        int idx = er * 256 + cc;
        *(uint2*)(g_Whi + idx) = Hi.u;
        *(uint2*)(g_Wlo + idx) = Lo.u;
    }
}

// ============================================================================
// K2: out = y @ W^T + bias, bf16 3-term split, fused K-chunks.
//   CTA tile 64x128, 8 warps (2M x 4N), warp tile 32x32, acc 32 regs ->
//   3 CTAs/SM (24 warps). 2-stage cp.async ring.
// ============================================================================
#define A_MAT 5120                 // 64 rows * 80B
#define B_MAT 10240                // 128 rows * 80B
#define STG (2*A_MAT + 2*B_MAT)    // 30720
#define SMEM_TOTAL (2 * STG)       // 61440

__global__ __launch_bounds__(256, 3) void gemm_mma_kernel(const float* __restrict__ bias,
                                                          float* __restrict__ out) {
    extern __shared__ __align__(16) char smem[];
    uint32_t sb = smem_u32(smem);
    int tid  = threadIdx.x;
    int wid  = tid >> 5;
    int lane = tid & 31;
    int bn = blockIdx.x * 128;
    int bm = blockIdx.y * 64;
    int wn = wid & 3;              // 4 N slices of 32
    int wm = wid >> 2;             // 2 M slices of 32

    float acc[2][4][4] = {};

    int arow = tid >> 2, aseg = tid & 3;
    int brow = tid >> 1, bsegb = (tid & 1) * 2;

    auto issue_loads = [&](int kc2, int slot) {
        int kb = kc2 * 32;
        uint32_t base = sb + slot * STG;
        {
            size_t aoff = (size_t)(bm + arow) * 256 + kb + aseg * 8;
            uint32_t da = base + arow * 80 + aseg * 16;
            CP_ASYNC16(da,          gmem_u64(g_yhi + aoff));
            CP_ASYNC16(da + A_MAT,  gmem_u64(g_ylo + aoff));
        }
        #pragma unroll
        for (int i = 0; i < 2; i++) {
            int bseg = bsegb + i;
            size_t boff = (size_t)(bn + brow) * 256 + kb + bseg * 8;
            uint32_t db = base + 2 * A_MAT + brow * 80 + bseg * 16;
            CP_ASYNC16(db,          gmem_u64(g_Whi + boff));
            CP_ASYNC16(db + B_MAT,  gmem_u64(g_Wlo + boff));
        }
    };

    issue_loads(0, 0); CP_COMMIT();
    issue_loads(1, 1); CP_COMMIT();

    #pragma unroll 1
    for (int kc = 0; kc < 8; kc++) {
        CP_WAIT(1);
        __syncthreads();

        int slot = kc & 1;
        uint32_t aHi = sb + slot * STG;
        uint32_t aLo = aHi + A_MAT;
        uint32_t bHi = aHi + 2 * A_MAT;
        uint32_t bLo = bHi + B_MAT;

        #pragma unroll
        for (int ks = 0; ks < 2; ks++) {
            uint32_t afh[2][4], afl[2][4], bf[2][4];
            #pragma unroll
            for (int mi = 0; mi < 2; mi++) {
                int row = wm * 32 + mi * 16 + (lane & 15);
                uint32_t ao = row * 80 + ks * 32 + (lane >> 4) * 16;
                LDMATRIX_X4(afh[mi][0], afh[mi][1], afh[mi][2], afh[mi][3], aHi + ao);
                LDMATRIX_X4(afl[mi][0], afl[mi][1], afl[mi][2], afl[mi][3], aLo + ao);
            }
            #pragma unroll
            for (int ng = 0; ng < 2; ng++) {
                int row = wn * 32 + ng * 16 + (lane & 15);
                uint32_t bo = row * 80 + ks * 32 + (lane >> 4) * 16;
                LDMATRIX_X4(bf[ng][0], bf[ng][1], bf[ng][2], bf[ng][3], bHi + bo);
            }
            // term0: Ahi*Bhi ; term1: Alo*Bhi
            #pragma unroll
            for (int mi = 0; mi < 2; mi++)
                #pragma unroll
                for (int ng = 0; ng < 2; ng++) {
                    MMA_16816(acc[mi][ng * 2 + 0], afh[mi], bf[ng][0], bf[ng][2]);
                    MMA_16816(acc[mi][ng * 2 + 1], afh[mi], bf[ng][1], bf[ng][3]);
                }
            #pragma unroll
            for (int mi = 0; mi < 2; mi++)
                #pragma unroll
                for (int ng = 0; ng < 2; ng++) {
                    MMA_16816(acc[mi][ng * 2 + 0], afl[mi], bf[ng][0], bf[ng][2]);
                    MMA_16816(acc[mi][ng * 2 + 1], afl[mi], bf[ng][1], bf[ng][3]);
                }
            // reload B with Blo; term2: Ahi*Blo
            #pragma unroll
            for (int ng = 0; ng < 2; ng++) {
                int row = wn * 32 + ng * 16 + (lane & 15);
                uint32_t bo = row * 80 + ks * 32 + (lane >> 4) * 16;
                LDMATRIX_X4(bf[ng][0], bf[ng][1], bf[ng][2], bf[ng][3], bLo + bo);
            }
            #pragma unroll
            for (int mi = 0; mi < 2; mi++)
                #pragma unroll
                for (int ng = 0; ng < 2; ng++) {
                    MMA_16816(acc[mi][ng * 2 + 0], afh[mi], bf[ng][0], bf[ng][2]);
                    MMA_16816(acc[mi][ng * 2 + 1], afh[mi], bf[ng][1], bf[ng][3]);
                }
        }
        __syncthreads();
        if (kc + 2 < 8) issue_loads(kc + 2, slot);
        CP_COMMIT();
    }

    // ---- epilogue ----
    #pragma unroll
    for (int mi = 0; mi < 2; mi++) {
        int r0 = bm + wm * 32 + mi * 16 + (lane >> 2);
        #pragma unroll
        for (int g = 0; g < 4; g++) {           // g = ng*2 + half
            int c = bn + wn * 32 + (g >> 1) * 16 + (g & 1) * 8 + (lane & 3) * 2;
            float b0 = __ldg(bias + c);
            float b1 = __ldg(bias + c + 1);
            float2 o0 = make_float2(acc[mi][g][0] + b0, acc[mi][g][1] + b1);
            float2 o1 = make_float2(acc[mi][g][2] + b0, acc[mi][g][3] + b1);
            *(float2*)(out + (size_t)r0 * 256 + c) = o0;
            *(float2*)(out + (size_t)(r0 + 8) * 256 + c) = o1;
        }
    }
}

// ============================================================================
extern "C" void kernel_launch(void* const* d_in, const int* in_sizes, int n_in,
                              void* d_out, int out_size) {
    const float* x  = (const float*)d_in[0];
    const float* vw = (const float*)d_in[1];
    const float* pw = (const float*)d_in[2];
    const float* pb = (const float*)d_in[3];
    float* out = (float*)d_out;

    cudaFuncSetAttribute(gemm_mma_kernel, cudaFuncAttributeMaxDynamicSharedMemorySize, SMEM_TOTAL);

    prep_kernel<<<512 + 64, 256>>>(x, vw, pw);
    gemm_mma_kernel<<<dim3(2, 512), 256, SMEM_TOTAL>>>(pb, out);
}

// round 8
// speedup vs baseline: 1.1628x; 1.1628x over previous
#include <cuda_runtime.h>
#include <cuda_fp16.h>
#include <stdint.h>
#include <math.h>

#define BB 8
#define HH 64
#define WW 64
#define CC 256
#define NPIX (BB*HH*WW)          // 32768

// ---------------- device scratch ----------------
__device__ __half g_yh[NPIX*CC];   // blurred x, hi fp16
__device__ __half g_yl[NPIX*CC];   // blurred x, lo fp16
__device__ __half g_Wh[CC*CC];     // fused weight W = proj_w @ v_w, fp16

// ---------------- helpers ----------------
__device__ __forceinline__ uint32_t smem_u32(const void* p) {
    uint32_t a;
    asm("{ .reg .u64 t; cvta.to.shared.u64 t, %1; cvt.u32.u64 %0, t; }" : "=r"(a) : "l"(p));
    return a;
}
__device__ __forceinline__ uint64_t gmem_u64(const void* p) {
    uint64_t a;
    asm("cvta.to.global.u64 %0, %1;" : "=l"(a) : "l"(p));
    return a;
}
#define CP_ASYNC16(sa, ga) \
    asm volatile("cp.async.cg.shared.global [%0], [%1], 16;" :: "r"(sa), "l"(ga))
#define CP_COMMIT() asm volatile("cp.async.commit_group;")
#define CP_WAIT(n)  asm volatile("cp.async.wait_group %0;" :: "n"(n))

#define LDMATRIX_X4(r0, r1, r2, r3, addr) \
    asm volatile("ldmatrix.sync.aligned.m8n8.x4.shared.b16 {%0,%1,%2,%3}, [%4];" \
        : "=r"(r0), "=r"(r1), "=r"(r2), "=r"(r3) : "r"(addr))

#define MMA_16816_F16(c, a, b0, b1) \
    asm volatile("mma.sync.aligned.m16n8k16.row.col.f32.f16.f16.f32 " \
        "{%0,%1,%2,%3}, {%4,%5,%6,%7}, {%8,%9}, {%0,%1,%2,%3};" \
        : "+f"((c)[0]), "+f"((c)[1]), "+f"((c)[2]), "+f"((c)[3]) \
        : "r"((a)[0]), "r"((a)[1]), "r"((a)[2]), "r"((a)[3]), "r"(b0), "r"(b1))

static __device__ __forceinline__ void split_f16(float v, __half& hi, __half& lo) {
    hi = __float2half_rn(v);
    lo = __float2half_rn(v - __half2float(hi));
}
static __device__ __forceinline__ float4 f4add(float4 a, float4 b) {
    return make_float4(a.x+b.x, a.y+b.y, a.z+b.z, a.w+b.w);
}

// ============================================================================
// K1: prep.
//  Blocks [0,512): blur, smem row-sharing. Block = (b, 16-row seg, 4-c4 cgroup).
//   Thread = (w, c4); 1 load/STS per row, 3 LDS, fp16-split store.
//  Blocks [512,576): W = proj_w @ v_w -> g_Wh (fp16).
// ============================================================================
__global__ __launch_bounds__(256) void prep_kernel(const float* __restrict__ x,
                                                   const float* __restrict__ vw,
                                                   const float* __restrict__ pw) {
    __shared__ float4 srow[2 * 256];    // 2 slots x (64 w x 4 c4) = 8KB
    int bid = blockIdx.x;
    int tid = threadIdx.x;
    if (bid < 512) {
        int b   = bid >> 6;           // 8
        int seg = (bid >> 4) & 3;     // 4 segments of 16 rows
        int cg  = bid & 15;           // 16 channel groups of 4 c4
        int h0  = seg * 16;
        int w   = tid >> 2;           // 0..63
        int c4i = tid & 3;
        int c4  = cg * 4 + c4i;
        const float e  = 2.718281828459045f;
        const float wo = 1.0f / (e + 8.0f);
        const float wd = e * wo - wo;
        const float4 Z = make_float4(0.f, 0.f, 0.f, 0.f);
        const float4* x4 = (const float4*)x;

        float4 hs0 = Z, hs1 = Z, xl0 = Z, xl1 = Z;

        auto gload = [&](int r) -> float4 {
            if (r < 0 || r >= HH) return Z;
            return x4[(((size_t)b * HH + r) * WW + w) * 64 + c4];
        };

        float4 vn = gload(h0 - 1);
        #pragma unroll 1
        for (int r = h0 - 1; r <= h0 + 16; r++) {
            int slot = (r - (h0 - 1)) & 1;
            float4 v = vn;
            if (r < h0 + 16) vn = gload(r + 1);
            srow[slot * 256 + w * 4 + c4i] = v;
            __syncthreads();
            float4 xl = (w > 0)  ? srow[slot * 256 + (w - 1) * 4 + c4i] : Z;
            float4 xc =            srow[slot * 256 + w * 4 + c4i];
            float4 xr = (w < 63) ? srow[slot * 256 + (w + 1) * 4 + c4i] : Z;
            float4 hsum = f4add(f4add(xl, xc), xr);

            if (r >= h0 + 1) {
                int h = r - 1;
                float4 o;
                o.x = wo * (hs0.x + hs1.x + hsum.x) + wd * xl0.x;
                o.y = wo * (hs0.y + hs1.y + hsum.y) + wd * xl0.y;
                o.z = wo * (hs0.z + hs1.z + hsum.z) + wd * xl0.z;
                o.w = wo * (hs0.w + hs1.w + hsum.w) + wd * xl0.w;
                union { __half h4[4]; uint2 u; } Hi, Lo;
                split_f16(o.x, Hi.h4[0], Lo.h4[0]);
                split_f16(o.y, Hi.h4[1], Lo.h4[1]);
                split_f16(o.z, Hi.h4[2], Lo.h4[2]);
                split_f16(o.w, Hi.h4[3], Lo.h4[3]);
                size_t oq = (((size_t)b * HH + h) * WW + w) * 64 + c4;  // uint2 units
                ((uint2*)g_yh)[oq] = Hi.u;
                ((uint2*)g_yl)[oq] = Lo.u;
            }
            hs0 = hs1; hs1 = hsum;
            xl0 = xl1; xl1 = xl;
        }
    } else {
        int q  = bid - 512;
        int e0 = (q >> 3) * 32;
        int c0 = (q & 7) * 32;
        int er = e0 + (tid >> 3);
        int cc = c0 + (tid & 7) * 4;
        float a0 = 0.f, a1 = 0.f, a2 = 0.f, a3 = 0.f;
        const float* prow = pw + er * 256;
        #pragma unroll 8
        for (int d = 0; d < 256; d++) {
            float a = prow[d];
            float4 v = *(const float4*)(vw + d * 256 + cc);
            a0 += a * v.x; a1 += a * v.y; a2 += a * v.z; a3 += a * v.w;
        }
        union { __half h4[4]; uint2 u; } Hi;
        Hi.h4[0] = __float2half_rn(a0);
        Hi.h4[1] = __float2half_rn(a1);
        Hi.h4[2] = __float2half_rn(a2);
        Hi.h4[3] = __float2half_rn(a3);
        *(uint2*)(g_Wh + er * 256 + cc) = Hi.u;
    }
}

// ============================================================================
// K2: out = y @ W^T + bias; fp16 2-term split: (yh + yl) * Wh, fp32 accum.
//   CTA tile 128x128, K-chunks of 64 (4 chunks), 3 matrices/stage (Ah,Al,B),
//   2-stage cp.async ring, 8 warps (4Mx2N), warp tile 32x64.
//   smem row stride 144B (128B data + 16 pad) -> conflict-free ldmatrix.
// ============================================================================
#define MAT 18432                    // 128 rows * 144B
#define STG (3 * MAT)                // 55296
#define SMEM_TOTAL (2 * STG)         // 110592

__global__ __launch_bounds__(256, 2) void gemm_mma_kernel(const float* __restrict__ bias,
                                                          float* __restrict__ out) {
    extern __shared__ __align__(16) char smem[];
    uint32_t sb = smem_u32(smem);
    int tid  = threadIdx.x;
    int wid  = tid >> 5;
    int lane = tid & 31;
    int bn = blockIdx.x * 128;
    int bm = blockIdx.y * 128;
    int wn = wid & 1;              // 2 N slices of 64
    int wm = wid >> 1;             // 4 M slices of 32

    float acc[2][8][4] = {};

    int ldrow  = tid >> 1;          // 0..127
    int ldc8b  = (tid & 1) * 4;     // 4 chunks of 16B per thread per matrix

    auto issue_loads = [&](int kc, int slot) {
        int kb = kc * 64;
        uint32_t base = sb + slot * STG;
        size_t aoff = (size_t)(bm + ldrow) * 256 + kb;
        size_t boff = (size_t)(bn + ldrow) * 256 + kb;
        #pragma unroll
        for (int i = 0; i < 4; i++) {
            int c8 = ldc8b + i;
            uint32_t d = base + ldrow * 144 + c8 * 16;
            CP_ASYNC16(d,            gmem_u64(g_yh + aoff + c8 * 8));
            CP_ASYNC16(d + MAT,      gmem_u64(g_yl + aoff + c8 * 8));
            CP_ASYNC16(d + 2 * MAT,  gmem_u64(g_Wh + boff + c8 * 8));
        }
    };

    issue_loads(0, 0); CP_COMMIT();
    issue_loads(1, 1); CP_COMMIT();

    #pragma unroll 1
    for (int kc = 0; kc < 4; kc++) {
        CP_WAIT(1);
        __syncthreads();

        int slot = kc & 1;
        uint32_t aH = sb + slot * STG;
        uint32_t aL = aH + MAT;
        uint32_t bH = aH + 2 * MAT;

        #pragma unroll
        for (int ks = 0; ks < 4; ks++) {
            uint32_t afh[2][4], afl[2][4], bf[4][4];
            #pragma unroll
            for (int mi = 0; mi < 2; mi++) {
                int row = wm * 32 + mi * 16 + (lane & 15);
                uint32_t ao = row * 144 + ks * 32 + (lane >> 4) * 16;
                LDMATRIX_X4(afh[mi][0], afh[mi][1], afh[mi][2], afh[mi][3], aH + ao);
                LDMATRIX_X4(afl[mi][0], afl[mi][1], afl[mi][2], afl[mi][3], aL + ao);
            }
            #pragma unroll
            for (int ng = 0; ng < 4; ng++) {
                int row = wn * 64 + ng * 16 + (lane & 15);
                uint32_t bo = row * 144 + ks * 32 + (lane >> 4) * 16;
                LDMATRIX_X4(bf[ng][0], bf[ng][1], bf[ng][2], bf[ng][3], bH + bo);
            }
            // term0: Ah * B
            #pragma unroll
            for (int mi = 0; mi < 2; mi++)
                #pragma unroll
                for (int ng = 0; ng < 4; ng++) {
                    MMA_16816_F16(acc[mi][ng * 2 + 0], afh[mi], bf[ng][0], bf[ng][2]);
                    MMA_16816_F16(acc[mi][ng * 2 + 1], afh[mi], bf[ng][1], bf[ng][3]);
                }
            // term1: Al * B (same B fragments)
            #pragma unroll
            for (int mi = 0; mi < 2; mi++)
                #pragma unroll
                for (int ng = 0; ng < 4; ng++) {
                    MMA_16816_F16(acc[mi][ng * 2 + 0], afl[mi], bf[ng][0], bf[ng][2]);
                    MMA_16816_F16(acc[mi][ng * 2 + 1], afl[mi], bf[ng][1], bf[ng][3]);
                }
        }
        __syncthreads();
        if (kc + 2 < 4) issue_loads(kc + 2, slot);
        CP_COMMIT();
    }

    // ---- epilogue ----
    #pragma unroll
    for (int mi = 0; mi < 2; mi++) {
        int r0 = bm + wm * 32 + mi * 16 + (lane >> 2);
        #pragma unroll
        for (int ni = 0; ni < 8; ni++) {
            int c = bn + wn * 64 + ni * 8 + (lane & 3) * 2;
            float b0 = __ldg(bias + c);
            float b1 = __ldg(bias + c + 1);
            float2 o0 = make_float2(acc[mi][ni][0] + b0, acc[mi][ni][1] + b1);
            float2 o1 = make_float2(acc[mi][ni][2] + b0, acc[mi][ni][3] + b1);
            *(float2*)(out + (size_t)r0 * 256 + c) = o0;
            *(float2*)(out + (size_t)(r0 + 8) * 256 + c) = o1;
        }
    }
}

// ============================================================================
extern "C" void kernel_launch(void* const* d_in, const int* in_sizes, int n_in,
                              void* d_out, int out_size) {
    const float* x  = (const float*)d_in[0];
    const float* vw = (const float*)d_in[1];
    const float* pw = (const float*)d_in[2];
    const float* pb = (const float*)d_in[3];
    float* out = (float*)d_out;

    cudaFuncSetAttribute(gemm_mma_kernel, cudaFuncAttributeMaxDynamicSharedMemorySize, SMEM_TOTAL);

    prep_kernel<<<512 + 64, 256>>>(x, vw, pw);
    gemm_mma_kernel<<<dim3(2, 256), 256, SMEM_TOTAL>>>(pb, out);
}

// round 9
// speedup vs baseline: 1.7857x; 1.5357x over previous
#include <cuda_runtime.h>
#include <cuda_fp16.h>
#include <stdint.h>
#include <math.h>

#define BB 8
#define HH 64
#define WW 64
#define CC 256
#define NPIX (BB*HH*WW)          // 32768

// ---------------- device scratch ----------------
__device__ __half g_yh[NPIX*CC];   // blurred x, fp16
__device__ __half g_Wh[CC*CC];     // fused weight W = proj_w @ v_w, fp16

// ---------------- helpers ----------------
__device__ __forceinline__ uint32_t smem_u32(const void* p) {
    uint32_t a;
    asm("{ .reg .u64 t; cvta.to.shared.u64 t, %1; cvt.u32.u64 %0, t; }" : "=r"(a) : "l"(p));
    return a;
}
__device__ __forceinline__ uint64_t gmem_u64(const void* p) {
    uint64_t a;
    asm("cvta.to.global.u64 %0, %1;" : "=l"(a) : "l"(p));
    return a;
}
#define CP_ASYNC16(sa, ga) \
    asm volatile("cp.async.cg.shared.global [%0], [%1], 16;" :: "r"(sa), "l"(ga))
#define CP_COMMIT() asm volatile("cp.async.commit_group;")
#define CP_WAIT(n)  asm volatile("cp.async.wait_group %0;" :: "n"(n))

#define LDMATRIX_X4(r0, r1, r2, r3, addr) \
    asm volatile("ldmatrix.sync.aligned.m8n8.x4.shared.b16 {%0,%1,%2,%3}, [%4];" \
        : "=r"(r0), "=r"(r1), "=r"(r2), "=r"(r3) : "r"(addr))

#define MMA_16816_F16(c, a, b0, b1) \
    asm volatile("mma.sync.aligned.m16n8k16.row.col.f32.f16.f16.f32 " \
        "{%0,%1,%2,%3}, {%4,%5,%6,%7}, {%8,%9}, {%0,%1,%2,%3};" \
        : "+f"((c)[0]), "+f"((c)[1]), "+f"((c)[2]), "+f"((c)[3]) \
        : "r"((a)[0]), "r"((a)[1]), "r"((a)[2]), "r"((a)[3]), "r"(b0), "r"(b1))

static __device__ __forceinline__ float4 f4add(float4 a, float4 b) {
    return make_float4(a.x+b.x, a.y+b.y, a.z+b.z, a.w+b.w);
}

// ============================================================================
// K1: prep.
//  Blocks [0,512): blur -> g_yh (fp16). Block = (b, 16-row seg, 4-c4 cgroup).
//   3-slot smem row ring, prefetch distance 2 (>=2 loads in flight/thread).
//  Blocks [512,576): W = proj_w @ v_w -> g_Wh (fp16).
// ============================================================================
__global__ __launch_bounds__(256) void prep_kernel(const float* __restrict__ x,
                                                   const float* __restrict__ vw,
                                                   const float* __restrict__ pw) {
    __shared__ float4 srow[3 * 256];    // 3 slots x (64 w x 4 c4) = 12KB
    int bid = blockIdx.x;
    int tid = threadIdx.x;
    if (bid < 512) {
        int b   = bid >> 6;           // 8
        int seg = (bid >> 4) & 3;     // 4 segments of 16 rows
        int cg  = bid & 15;           // 16 channel groups of 4 c4
        int h0  = seg * 16;
        int w   = tid >> 2;           // 0..63
        int c4i = tid & 3;
        int c4  = cg * 4 + c4i;
        const float e  = 2.718281828459045f;
        const float wo = 1.0f / (e + 8.0f);
        const float wd = e * wo - wo;
        const float4 Z = make_float4(0.f, 0.f, 0.f, 0.f);
        const float4* x4 = (const float4*)x;

        auto gload = [&](int r) -> float4 {
            if (r < 0 || r >= HH || r > h0 + 16) return Z;
            return x4[(((size_t)b * HH + r) * WW + w) * 64 + c4];
        };

        float4 hs0 = Z, hs1 = Z, xl0 = Z, xl1 = Z;

        // prologue: rows h0-1, h0, h0+1 in flight; row h0-1 staged
        float4 v0 = gload(h0 - 1);
        float4 v1 = gload(h0);
        float4 v2 = gload(h0 + 1);
        srow[0 * 256 + w * 4 + c4i] = v0;
        float4 vStore = v1;     // row h0 (STS at i=0)
        float4 vIn    = v2;     // row h0+1 (STS at i=1)

        #pragma unroll 1
        for (int i = 0; i <= 17; i++) {        // r = h0-1+i
            int r = h0 - 1 + i;
            srow[((i + 1) % 3) * 256 + w * 4 + c4i] = vStore;   // row r+1
            float4 tmp = gload(r + 3);                           // prefetch (dist 2)
            __syncthreads();                                     // rows <= r+1 visible

            int slot = i % 3;
            float4 xl = (w > 0)  ? srow[slot * 256 + (w - 1) * 4 + c4i] : Z;
            float4 xc =            srow[slot * 256 + w * 4 + c4i];
            float4 xr = (w < 63) ? srow[slot * 256 + (w + 1) * 4 + c4i] : Z;
            float4 hsum = f4add(f4add(xl, xc), xr);

            if (r >= h0 + 1) {
                int h = r - 1;
                float4 o;
                o.x = wo * (hs0.x + hs1.x + hsum.x) + wd * xl0.x;
                o.y = wo * (hs0.y + hs1.y + hsum.y) + wd * xl0.y;
                o.z = wo * (hs0.z + hs1.z + hsum.z) + wd * xl0.z;
                o.w = wo * (hs0.w + hs1.w + hsum.w) + wd * xl0.w;
                union { __half h4[4]; uint2 u; } Hi;
                Hi.h4[0] = __float2half_rn(o.x);
                Hi.h4[1] = __float2half_rn(o.y);
                Hi.h4[2] = __float2half_rn(o.z);
                Hi.h4[3] = __float2half_rn(o.w);
                size_t oq = (((size_t)b * HH + h) * WW + w) * 64 + c4;  // uint2 units
                ((uint2*)g_yh)[oq] = Hi.u;
            }
            hs0 = hs1; hs1 = hsum;
            xl0 = xl1; xl1 = xl;
            vStore = vIn; vIn = tmp;
        }
    } else {
        int q  = bid - 512;
        int e0 = (q >> 3) * 32;
        int c0 = (q & 7) * 32;
        int er = e0 + (tid >> 3);
        int cc = c0 + (tid & 7) * 4;
        float a0 = 0.f, a1 = 0.f, a2 = 0.f, a3 = 0.f;
        const float* prow = pw + er * 256;
        #pragma unroll 8
        for (int d = 0; d < 256; d++) {
            float a = prow[d];
            float4 v = *(const float4*)(vw + d * 256 + cc);
            a0 += a * v.x; a1 += a * v.y; a2 += a * v.z; a3 += a * v.w;
        }
        union { __half h4[4]; uint2 u; } Hi;
        Hi.h4[0] = __float2half_rn(a0);
        Hi.h4[1] = __float2half_rn(a1);
        Hi.h4[2] = __float2half_rn(a2);
        Hi.h4[3] = __float2half_rn(a3);
        *(uint2*)(g_Wh + er * 256 + cc) = Hi.u;
    }
}

// ============================================================================
// K2: out = y @ W^T + bias; single fp16 term, fp32 accum.
//   CTA 128x128. B (weight N-tile, 128 rows x full K=256) RESIDENT in smem,
//   loaded once. A streamed in K=32 chunks through a 3-slot cp.async ring.
//   8 warps (4Mx2N), warp tile 32x64. One syncthreads per chunk.
//   B row stride 528B, A row stride 80B -> conflict-free ldmatrix.
// ============================================================================
#define B_STRIDE 528
#define B_BYTES  (128 * B_STRIDE)        // 67584
#define A_SLOT   10240                   // 128 * 80
#define SMEM_TOTAL (B_BYTES + 3 * A_SLOT)  // 98304 (96KB) -> 2 CTAs/SM

__global__ __launch_bounds__(256, 2) void gemm_mma_kernel(const float* __restrict__ bias,
                                                          float* __restrict__ out) {
    extern __shared__ __align__(16) char smem[];
    uint32_t sbB = smem_u32(smem);
    uint32_t sbA = sbB + B_BYTES;
    int tid  = threadIdx.x;
    int wid  = tid >> 5;
    int lane = tid & 31;
    int bn = blockIdx.x * 128;
    int bm = blockIdx.y * 128;
    int wn = wid & 1;              // 2 N slices of 64
    int wm = wid >> 1;             // 4 M slices of 32

    float acc[2][8][4] = {};

    // ---- one-time B load: 128 rows x 512B ----
    #pragma unroll
    for (int i = 0; i < 16; i++) {
        int q = i * 256 + tid;          // 4096 16B-chunks
        int row = q >> 5, c16 = q & 31;
        CP_ASYNC16(sbB + row * B_STRIDE + c16 * 16,
                   gmem_u64(g_Wh + (size_t)(bn + row) * 256 + c16 * 8));
    }

    auto issue_A = [&](int kc, int slot) {
        #pragma unroll
        for (int j = 0; j < 2; j++) {
            int q = tid * 2 + j;        // 512 chunks
            int row = q >> 2, seg = q & 3;
            CP_ASYNC16(sbA + slot * A_SLOT + row * 80 + seg * 16,
                       gmem_u64(g_yh + (size_t)(bm + row) * 256 + kc * 32 + seg * 8));
        }
    };

    issue_A(0, 0); CP_COMMIT();     // C0 = B + A0
    issue_A(1, 1); CP_COMMIT();     // C1 = A1

    #pragma unroll 1
    for (int kc = 0; kc < 8; kc++) {
        if (kc < 7) { CP_WAIT(1); } else { CP_WAIT(0); }
        __syncthreads();
        if (kc + 2 < 8) { issue_A(kc + 2, (kc + 2) % 3); CP_COMMIT(); }

        uint32_t aB = sbA + (kc % 3) * A_SLOT;

        #pragma unroll
        for (int ks = 0; ks < 2; ks++) {
            uint32_t af[2][4], bf[4][4];
            #pragma unroll
            for (int mi = 0; mi < 2; mi++) {
                int row = wm * 32 + mi * 16 + (lane & 15);
                uint32_t ao = row * 80 + ks * 32 + (lane >> 4) * 16;
                LDMATRIX_X4(af[mi][0], af[mi][1], af[mi][2], af[mi][3], aB + ao);
            }
            #pragma unroll
            for (int ng = 0; ng < 4; ng++) {
                int row = wn * 64 + ng * 16 + (lane & 15);
                uint32_t bo = row * B_STRIDE + kc * 64 + ks * 32 + (lane >> 4) * 16;
                LDMATRIX_X4(bf[ng][0], bf[ng][1], bf[ng][2], bf[ng][3], sbB + bo);
            }
            #pragma unroll
            for (int mi = 0; mi < 2; mi++)
                #pragma unroll
                for (int ng = 0; ng < 4; ng++) {
                    MMA_16816_F16(acc[mi][ng * 2 + 0], af[mi], bf[ng][0], bf[ng][2]);
                    MMA_16816_F16(acc[mi][ng * 2 + 1], af[mi], bf[ng][1], bf[ng][3]);
                }
        }
    }

    // ---- epilogue ----
    #pragma unroll
    for (int mi = 0; mi < 2; mi++) {
        int r0 = bm + wm * 32 + mi * 16 + (lane >> 2);
        #pragma unroll
        for (int ni = 0; ni < 8; ni++) {
            int c = bn + wn * 64 + ni * 8 + (lane & 3) * 2;
            float b0 = __ldg(bias + c);
            float b1 = __ldg(bias + c + 1);
            float2 o0 = make_float2(acc[mi][ni][0] + b0, acc[mi][ni][1] + b1);
            float2 o1 = make_float2(acc[mi][ni][2] + b0, acc[mi][ni][3] + b1);
            *(float2*)(out + (size_t)r0 * 256 + c) = o0;
            *(float2*)(out + (size_t)(r0 + 8) * 256 + c) = o1;
        }
    }
}

// ============================================================================
extern "C" void kernel_launch(void* const* d_in, const int* in_sizes, int n_in,
                              void* d_out, int out_size) {
    const float* x  = (const float*)d_in[0];
    const float* vw = (const float*)d_in[1];
    const float* pw = (const float*)d_in[2];
    const float* pb = (const float*)d_in[3];
    float* out = (float*)d_out;

    cudaFuncSetAttribute(gemm_mma_kernel, cudaFuncAttributeMaxDynamicSharedMemorySize, SMEM_TOTAL);

    prep_kernel<<<512 + 64, 256>>>(x, vw, pw);
    gemm_mma_kernel<<<dim3(2, 256), 256, SMEM_TOTAL>>>(pb, out);
}